// round 17
// baseline (speedup 1.0000x reference)
#include <cuda_runtime.h>

// x: (8, 64, 128, 128) fp32  ->  out: (8, 64, 384, 384) fp32
//
// Separable 3x half-pixel resample (RATIO=0.5, KS=3 collapse).
// Row dedup: distinct output rows: center(i)=H(x[i]) -> row 3i+1;
// avg(i)=H(0.5*(x[i]+x[i+1])) -> rows 3i+2, 3i+3; row 0 = avg(0);
// row 383 = avg(126) (= avg(127) via reflect 128->126).
// H(): out col 3j+kj: kj=0 -> h[j-1], kj=1 -> c[j], kj=2 -> h[j];
// h[j] = 0.5*(c[j]+c[refl(j+1)]); reflect: -1 -> 1, 128 -> 126.
//
// R17: warp owns an input-row PAIR (p, p+1) -> six output rows.
//  - 3x LDG.128 (rows p, p+1, p+2-with-reflect) instead of 4 for 2 rows
//  - smem holds float4 {center(p), avg(p), center(p+1), avg(p+1)} per col:
//    each gather position is ONE LDS.128 serving all six output rows;
//    index math (q, r, reflect, swizzle) amortized over 6 rows
//  - swizzle m = q + (q>>2): STS.128 stay contiguous (slots 5u..5u+3,
//    byte addrs 80u -> bank-clean), breaks the q/q+8 128B collision
//  - all output stores: coalesced full-sector STG.128 .cs streaming
// DRAM ceiling 68-70% validated across LSU/TMA/STG.256 paths; this round
// halves remaining gather/ALU pressure per output row.

#define H 128
#define W 128
#define W4 (W / 4)
#define OW 384
#define OW4 (OW / 4)
#define NW 8                  // warps per block = row-pairs per block
#define CS4 160               // float4 slots per warp (max swz4(127)=158)

__device__ __forceinline__ int swz4(int q) { return q + (q >> 2); }

__device__ __forceinline__ float4 hout(float c, float c1, float t, int r)
{
    const float h0 = 0.5f * (c + c1);
    const float ex = 0.5f * (t + ((r == 0) ? c : c1));
    float4 v;
    v.x = (r == 0) ? ex : ((r == 1) ? c : h0);
    v.y = (r == 0) ? c  : h0;
    v.z = (r == 2) ? c1 : h0;
    v.w = (r == 2) ? ex : ((r == 1) ? c1 : h0);
    return v;
}

__global__ __launch_bounds__(NW * 32) void rf_scale_kernel(
    const float4* __restrict__ x, float4* __restrict__ out)
{
    __shared__ float4 Cs[NW][CS4];  // Cs[w][m] = {c(p), a(p), c(p+1), a(p+1)}

    const int lane = threadIdx.x & 31;
    const int w    = threadIdx.x >> 5;

    const int p  = ((blockIdx.x * NW) + w) << 1;   // even input row 0..126
    const int bc = blockIdx.y;

    const float4* __restrict__ xin = x + (size_t)bc * (H * W4);

    const int p2 = (p + 2 < H) ? p + 2 : H - 2;    // reflect: 128 -> 126
    const float4 b = xin[p        * W4 + lane];    // row p
    const float4 d = xin[(p + 1)  * W4 + lane];    // row p+1
    const float4 e = xin[p2       * W4 + lane];    // row p+2 (reflected)

    // avg(p) and avg(p+1)  (avg(127) = avg(126) via reflect: e == row 126)
    const float4 a0 = make_float4(0.5f * (b.x + d.x), 0.5f * (b.y + d.y),
                                  0.5f * (b.z + d.z), 0.5f * (b.w + d.w));
    const float4 a1 = make_float4(0.5f * (d.x + e.x), 0.5f * (d.y + e.y),
                                  0.5f * (d.z + e.z), 0.5f * (d.w + e.w));

    // Interleaved per-column store: slot(4u+k) = {b[k], a0[k], d[k], a1[k]}.
    // swz4(4u+k) = 5u + k  -> 4 contiguous STS.128 at byte base 80u.
    {
        float4* ps = &Cs[w][5 * lane];
        ps[0] = make_float4(b.x, a0.x, d.x, a1.x);
        ps[1] = make_float4(b.y, a0.y, d.y, a1.y);
        ps[2] = make_float4(b.z, a0.z, d.z, a1.z);
        ps[3] = make_float4(b.w, a0.w, d.w, a1.w);
    }
    __syncwarp();

    const float4* __restrict__ C = Cs[w];

    float4* __restrict__ obase =
        out + (size_t)bc * (OW * OW4) + (size_t)(3 * p) * OW4;

    const bool lastpair = (p == H - 2);            // p+1 == 127

    #pragma unroll
    for (int s = 0; s < 3; s++) {
        const int g  = lane + (s << 5);                       // 0..95
        const int fg = g << 2;
        const int q  = (int)(((unsigned)fg * 21846u) >> 16);  // fg/3 (exact)
        const int r  = fg - 3 * q;

        const int qt = (r == 0) ? ((q == 0) ? 1 : q - 1)
                                : ((q == W - 2) ? (W - 2) : q + 2);

        const float4 P  = C[swz4(q)];
        const float4 P1 = C[swz4(q + 1)];
        const float4 Pt = C[swz4(qt)];

        // input row p: center -> 3p+1, avg -> 3p+2, 3p+3 (row 0 = avg(0))
        const float4 vc0 = hout(P.x, P1.x, Pt.x, r);
        const float4 va0 = hout(P.y, P1.y, Pt.y, r);
        __stcs(&obase[OW4 + g], vc0);
        __stcs(&obase[2 * OW4 + g], va0);
        __stcs(&obase[3 * OW4 + g], va0);
        if (p == 0) __stcs(&obase[g], va0);

        // input row p+1: center -> 3p+4; avg -> 3p+5, 3p+6
        // (lastpair: avg(127)=avg(126) -> row 383 = 3p+5 only)
        const float4 vc1 = hout(P.z, P1.z, Pt.z, r);
        const float4 va1 = hout(P.w, P1.w, Pt.w, r);
        __stcs(&obase[4 * OW4 + g], vc1);
        __stcs(&obase[5 * OW4 + g], va1);
        if (!lastpair) __stcs(&obase[6 * OW4 + g], va1);
    }
}

extern "C" void kernel_launch(void* const* d_in, const int* in_sizes, int n_in,
                              void* d_out, int out_size)
{
    const float4* x = (const float4*)d_in[0];
    float4* out = (float4*)d_out;

    const int n_bc = in_sizes[0] / (H * W);   // 512

    dim3 grid((H / 2) / NW, n_bc);            // (8, 512)
    dim3 block(NW * 32);                      // 256
    rf_scale_kernel<<<grid, block>>>(x, out);
}